// round 1
// baseline (speedup 1.0000x reference)
#include <cuda_runtime.h>
#include <math.h>

#define BB 4
#define SS 2048
#define DD 1024
#define M1 (BB*SS)

// Scratch (device globals: allocation-free, harness-legal)
__device__ float g_Q[(size_t)M1 * DD];
__device__ float g_K[(size_t)M1 * DD];
__device__ float g_V[(size_t)M1 * DD];
__device__ float g_S[(size_t)BB * SS * SS];

// ---------------------------------------------------------------------------
// Tiled fp32 GEMM. NT: C[m,n] = sum_k A[m*K+k]*B[n*K+k] (both K-contiguous).
// NN: C[m,n] = sum_k A[m*K+k]*B[k*N+n]. 128x128 tile, BK=8, 256 threads,
// 8x8 per-thread microtile, double-buffered smem, float4 loads.
// All of M,N divisible by 128 and K by 8 (guaranteed by problem shapes).
// ---------------------------------------------------------------------------
template<bool NT, bool HAS_BIAS>
__global__ __launch_bounds__(256, 2)
void gemm_k(const float* __restrict__ A, const float* __restrict__ Bm,
            const float* __restrict__ bias, float* __restrict__ C,
            int M, int N, int K, long sA, long sB, long sC)
{
    A  += (size_t)blockIdx.z * sA;
    Bm += (size_t)blockIdx.z * sB;
    C  += (size_t)blockIdx.z * sC;

    __shared__ float As[2][8][132];
    __shared__ float Bs[2][8][132];

    const int tid = threadIdx.x;
    const int m0 = blockIdx.y * 128;
    const int n0 = blockIdx.x * 128;

    // A tile load: 128 rows x 8 k, one float4 per thread along k
    const int ar = tid >> 1;            // 0..127
    const int ak = (tid & 1) * 4;       // 0 or 4
    const float* Aptr = A + (size_t)(m0 + ar) * K + ak;

    // B tile load
    int br, bc;
    const float* Bptr;
    if (NT) {
        br = tid >> 1; bc = (tid & 1) * 4;                 // row n, col k
        Bptr = Bm + (size_t)(n0 + br) * K + bc;
    } else {
        br = tid >> 5; bc = (tid & 31) * 4;                // row k, col n
        Bptr = Bm + (size_t)br * N + n0 + bc;
    }

    const int tx = tid & 15, ty = tid >> 4;
    const int row0 = ty * 8, col0 = tx * 8;

    float acc[8][8];
    #pragma unroll
    for (int i = 0; i < 8; i++)
        #pragma unroll
        for (int j = 0; j < 8; j++) acc[i][j] = 0.f;

    const int NK = K >> 3;

    // preload tile 0
    {
        float4 a4 = *(const float4*)Aptr;
        As[0][ak+0][ar] = a4.x; As[0][ak+1][ar] = a4.y;
        As[0][ak+2][ar] = a4.z; As[0][ak+3][ar] = a4.w;
        float4 b4 = *(const float4*)Bptr;
        if (NT) {
            Bs[0][bc+0][br] = b4.x; Bs[0][bc+1][br] = b4.y;
            Bs[0][bc+2][br] = b4.z; Bs[0][bc+3][br] = b4.w;
        } else {
            *(float4*)&Bs[0][br][bc] = b4;
        }
    }
    __syncthreads();

    int buf = 0;
    for (int kt = 0; kt < NK; kt++) {
        float4 na, nb;
        const bool more = (kt + 1 < NK);
        if (more) {
            na = *(const float4*)(Aptr + (size_t)(kt + 1) * 8);
            nb = NT ? *(const float4*)(Bptr + (size_t)(kt + 1) * 8)
                    : *(const float4*)(Bptr + (size_t)(kt + 1) * 8 * N);
        }

        #pragma unroll
        for (int k = 0; k < 8; k++) {
            float a[8], b[8];
            *(float4*)&a[0] = *(const float4*)&As[buf][k][row0];
            *(float4*)&a[4] = *(const float4*)&As[buf][k][row0 + 4];
            *(float4*)&b[0] = *(const float4*)&Bs[buf][k][col0];
            *(float4*)&b[4] = *(const float4*)&Bs[buf][k][col0 + 4];
            #pragma unroll
            for (int i = 0; i < 8; i++)
                #pragma unroll
                for (int j = 0; j < 8; j++)
                    acc[i][j] += a[i] * b[j];
        }

        if (more) {
            const int nb_ = buf ^ 1;
            As[nb_][ak+0][ar] = na.x; As[nb_][ak+1][ar] = na.y;
            As[nb_][ak+2][ar] = na.z; As[nb_][ak+3][ar] = na.w;
            if (NT) {
                Bs[nb_][bc+0][br] = nb.x; Bs[nb_][bc+1][br] = nb.y;
                Bs[nb_][bc+2][br] = nb.z; Bs[nb_][bc+3][br] = nb.w;
            } else {
                *(float4*)&Bs[nb_][br][bc] = nb;
            }
        }
        __syncthreads();
        buf ^= 1;
    }

    // epilogue
    float bv_[8];
    #pragma unroll
    for (int j = 0; j < 8; j++)
        bv_[j] = HAS_BIAS ? bias[n0 + col0 + j] : 0.f;

    #pragma unroll
    for (int i = 0; i < 8; i++) {
        float* cp = C + (size_t)(m0 + row0 + i) * N + n0 + col0;
        float4 o0, o1;
        o0.x = acc[i][0] + bv_[0]; o0.y = acc[i][1] + bv_[1];
        o0.z = acc[i][2] + bv_[2]; o0.w = acc[i][3] + bv_[3];
        o1.x = acc[i][4] + bv_[4]; o1.y = acc[i][5] + bv_[5];
        o1.z = acc[i][6] + bv_[6]; o1.w = acc[i][7] + bv_[7];
        *(float4*)cp = o0;
        *(float4*)(cp + 4) = o1;
    }
}

// ---------------------------------------------------------------------------
// Rowwise softmax over 2048 elements, in place. One 256-thread CTA per row.
// ---------------------------------------------------------------------------
__global__ __launch_bounds__(256)
void softmax_k()
{
    float* p = g_S + (size_t)blockIdx.x * SS;
    const int t = threadIdx.x;
    const int lane = t & 31, w = t >> 5;
    __shared__ float red[8];

    float v[8];
    float mx = -3.4e38f;
    #pragma unroll
    for (int i = 0; i < 8; i++) {
        v[i] = p[t + i * 256];
        mx = fmaxf(mx, v[i]);
    }
    #pragma unroll
    for (int o = 16; o; o >>= 1) mx = fmaxf(mx, __shfl_xor_sync(0xffffffffu, mx, o));
    if (lane == 0) red[w] = mx;
    __syncthreads();
    float m = red[0];
    #pragma unroll
    for (int i = 1; i < 8; i++) m = fmaxf(m, red[i]);

    float s = 0.f;
    #pragma unroll
    for (int i = 0; i < 8; i++) {
        v[i] = expf(v[i] - m);
        s += v[i];
    }
    #pragma unroll
    for (int o = 16; o; o >>= 1) s += __shfl_xor_sync(0xffffffffu, s, o);
    __syncthreads();                 // all reads of red (max) done
    if (lane == 0) red[w] = s;
    __syncthreads();
    s = 0.f;
    #pragma unroll
    for (int i = 0; i < 8; i++) s += red[i];

    const float inv = 1.0f / s;
    #pragma unroll
    for (int i = 0; i < 8; i++) p[t + i * 256] = v[i] * inv;
}

extern "C" void kernel_launch(void* const* d_in, const int* in_sizes, int n_in,
                              void* d_out, int out_size)
{
    const float* x  = (const float*)d_in[0];
    const float* Wq = (const float*)d_in[1];
    const float* bq = (const float*)d_in[2];
    const float* Wk = (const float*)d_in[3];
    const float* bk = (const float*)d_in[4];
    const float* Wv = (const float*)d_in[5];
    const float* bv = (const float*)d_in[6];
    float* out = (float*)d_out;

    float *Qp, *Kp, *Vp, *Sp;
    cudaGetSymbolAddress((void**)&Qp, g_Q);
    cudaGetSymbolAddress((void**)&Kp, g_K);
    cudaGetSymbolAddress((void**)&Vp, g_V);
    cudaGetSymbolAddress((void**)&Sp, g_S);

    dim3 blk(256);

    // 1) QKV projections: [8192,1024] = x[8192,1024] @ W^T + b   (NT)
    dim3 g1(DD / 128, M1 / 128, 1);
    gemm_k<true,  true><<<g1, blk>>>(x, Wq, bq, Qp, M1, DD, DD, 0, 0, 0);
    gemm_k<true,  true><<<g1, blk>>>(x, Wk, bk, Kp, M1, DD, DD, 0, 0, 0);
    gemm_k<true,  true><<<g1, blk>>>(x, Wv, bv, Vp, M1, DD, DD, 0, 0, 0);

    // 2) scores[b] = Q_b @ K_b^T  (NT, batched over z)
    dim3 g2(SS / 128, SS / 128, BB);
    gemm_k<true, false><<<g2, blk>>>(Qp, Kp, nullptr, Sp, SS, SS, DD,
                                     (long)SS * DD, (long)SS * DD, (long)SS * SS);

    // 3) rowwise softmax in place
    softmax_k<<<BB * SS, 256>>>();

    // 4) out[b] = P_b @ V_b  (NN, batched over z)
    dim3 g3(DD / 128, SS / 128, BB);
    gemm_k<false, false><<<g3, blk>>>(Sp, Vp, nullptr, out, SS, DD, SS,
                                      (long)SS * SS, (long)SS * DD, (long)SS * DD);
}

// round 3
// speedup vs baseline: 3.9037x; 3.9037x over previous
#include <cuda_runtime.h>
#include <cuda_bf16.h>
#include <stdint.h>
#include <math.h>

#define BB 4
#define SS 2048
#define DD 1024
#define M1 (BB*SS)

// ---------------------------------------------------------------------------
// Scratch (device globals; allocation-free). GEMM operands stored "packed":
// one uint32 per logical fp32 element = (bf16 hi) | (bf16 lo << 16).
// ---------------------------------------------------------------------------
__device__ uint32_t g_xp [(size_t)M1*DD];
__device__ uint32_t g_Wqp[(size_t)DD*DD];
__device__ uint32_t g_Wkp[(size_t)DD*DD];
__device__ uint32_t g_Wvp[(size_t)DD*DD];
__device__ uint32_t g_Qp [(size_t)M1*DD];
__device__ uint32_t g_Kp [(size_t)M1*DD];
__device__ uint32_t g_Vtp[(size_t)BB*DD*SS];      // V transposed: [b][dim][seq]
__device__ float    g_S  [(size_t)BB*SS*SS];      // logits fp32, then packed P in place

// ---------------------------------------------------------------------------
__device__ __forceinline__ uint32_t split_pack(float v){
    __nv_bfloat16 h = __float2bfloat16(v);
    float hf = __bfloat162float(h);
    __nv_bfloat16 l = __float2bfloat16(v - hf);
    return (uint32_t)__bfloat16_as_ushort(h) | ((uint32_t)__bfloat16_as_ushort(l) << 16);
}
__device__ __forceinline__ uint32_t s2u(const void* p){
    uint32_t a;
    asm("{ .reg .u64 t; cvta.to.shared.u64 t, %1; cvt.u32.u64 %0, t; }" : "=r"(a) : "l"(p));
    return a;
}

#define LDSM4(r0,r1,r2,r3,a) \
    asm volatile("ldmatrix.sync.aligned.m8n8.x4.shared.b16 {%0,%1,%2,%3}, [%4];" \
        : "=r"(r0),"=r"(r1),"=r"(r2),"=r"(r3) : "r"(a))

#define MMA16816(c,a0,a1,a2,a3,b0,b1) \
    asm volatile("mma.sync.aligned.m16n8k16.row.col.f32.bf16.bf16.f32 " \
        "{%0,%1,%2,%3},{%4,%5,%6,%7},{%8,%9},{%0,%1,%2,%3};" \
        : "+f"((c)[0]),"+f"((c)[1]),"+f"((c)[2]),"+f"((c)[3]) \
        : "r"(a0),"r"(a1),"r"(a2),"r"(a3),"r"(b0),"r"(b1))

// ---------------------------------------------------------------------------
// HMMA GEMM: C[m,n] = sum_k A[m,k]*B[n,k]  (both packed hi/lo bf16, K-major).
// CTA tile 128x128, 512 threads = 16 warps (4x4), warp tile 32x32, KC=32,
// double-buffered smem with hi/lo de-interleave (pitch 40 bf16 = conflict-free
// ldmatrix). 3 products: Ah*Bh + Al*Bh + Ah*Bl, fp32 accumulate.
// EPI: 0 = bias + split-pack   1 = bias + split-pack transposed ([b][d][s])
//      2 = raw fp32
// ---------------------------------------------------------------------------
#define PITCH 40                 // bf16 elements per smem row (32 + 8 pad)
#define TILEB (128*PITCH*2)      // 10240 bytes per bf16 tile
#define BUFB  (4*TILEB)          // Ah,Al,Bh,Bl
#define SMEMSZ (2*BUFB > 128*132*4 ? 2*BUFB : 128*132*4)   // 81920

template<int EPI>
__global__ __launch_bounds__(512, 1)
void gemm_t(const uint32_t* __restrict__ Ap, const uint32_t* __restrict__ Bp,
            const float* __restrict__ bias, void* __restrict__ Cout,
            int Kg, int ldc, long sA, long sB, long sC)
{
    extern __shared__ __align__(128) char dsm[];

    const int tid = threadIdx.x;
    const int wid = tid >> 5, lane = tid & 31;
    const int warp_m = wid & 3, warp_n = wid >> 2;   // 4x4 warp grid
    const int m0 = blockIdx.y * 128;
    const int n0 = blockIdx.x * 128;
    const int z  = blockIdx.z;

    Ap += (size_t)z * sA;
    Bp += (size_t)z * sB;

    const uint32_t sb = s2u(dsm);

    // global load coords: e = tid + i*512 ; r = e>>3 (row 0..127), q = e&7 (k-quad)
    const int gr = tid >> 3, gq = tid & 7;

    float acc[2][4][4];
    #pragma unroll
    for (int f = 0; f < 2; f++)
        #pragma unroll
        for (int b = 0; b < 4; b++)
            #pragma unroll
            for (int j = 0; j < 4; j++) acc[f][b][j] = 0.f;

    // ldmatrix base addresses (buffer 0): row = lane%16, col-phase = (lane/16)*8
    const int lrow = lane & 15, lcol = (lane >> 4) * 8;
    uint32_t aA[2], aB[2];
    #pragma unroll
    for (int f = 0; f < 2; f++)
        aA[f] = sb + ((warp_m*32 + f*16 + lrow) * PITCH + lcol) * 2;
    #pragma unroll
    for (int p = 0; p < 2; p++)
        aB[p] = sb + 2*TILEB + ((warp_n*32 + p*16 + lrow) * PITCH + lcol) * 2;

    const int NC = Kg >> 5;   // KC = 32

    // ---- store chunk (2 uint4 for A, 2 for B) into smem buffer ----
    auto store_chunk = [&](int buf, const uint4* va, const uint4* vb){
        char* tb = dsm + buf * BUFB;
        #pragma unroll
        for (int i = 0; i < 2; i++) {
            int r = gr + i*64;
            uint32_t off = (r * PITCH + gq * 4) * 2;
            uint4 x = va[i];
            *(uint2*)(tb + off) =
                make_uint2(__byte_perm(x.x, x.y, 0x5410), __byte_perm(x.z, x.w, 0x5410));
            *(uint2*)(tb + TILEB + off) =
                make_uint2(__byte_perm(x.x, x.y, 0x7632), __byte_perm(x.z, x.w, 0x7632));
            x = vb[i];
            *(uint2*)(tb + 2*TILEB + off) =
                make_uint2(__byte_perm(x.x, x.y, 0x5410), __byte_perm(x.z, x.w, 0x5410));
            *(uint2*)(tb + 3*TILEB + off) =
                make_uint2(__byte_perm(x.x, x.y, 0x7632), __byte_perm(x.z, x.w, 0x7632));
        }
    };
    auto load_chunk = [&](int c, uint4* va, uint4* vb){
        const int kc0 = c << 5;
        #pragma unroll
        for (int i = 0; i < 2; i++) {
            int r = gr + i*64;
            va[i] = *(const uint4*)(Ap + (size_t)(m0 + r) * Kg + kc0 + gq * 4);
            vb[i] = *(const uint4*)(Bp + (size_t)(n0 + r) * Kg + kc0 + gq * 4);
        }
    };

    {   // preload chunk 0
        uint4 va[2], vb[2];
        load_chunk(0, va, vb);
        store_chunk(0, va, vb);
    }
    __syncthreads();

    for (int c = 0; c < NC; c++) {
        const int buf = c & 1;
        uint4 va[2], vb[2];
        const bool more = (c + 1 < NC);
        if (more) load_chunk(c + 1, va, vb);

        const uint32_t bo = buf * BUFB;
        #pragma unroll
        for (int ks = 0; ks < 2; ks++) {
            const uint32_t ko = ks * 32;   // 16 bf16 = 32 bytes
            uint32_t ah[2][4], al[2][4], bh[2][4], bl[2][4];
            #pragma unroll
            for (int f = 0; f < 2; f++) {
                LDSM4(ah[f][0],ah[f][1],ah[f][2],ah[f][3], aA[f] + bo + ko);
                LDSM4(al[f][0],al[f][1],al[f][2],al[f][3], aA[f] + bo + ko + TILEB);
            }
            #pragma unroll
            for (int p = 0; p < 2; p++) {
                LDSM4(bh[p][0],bh[p][1],bh[p][2],bh[p][3], aB[p] + bo + ko);
                LDSM4(bl[p][0],bl[p][1],bl[p][2],bl[p][3], aB[p] + bo + ko + TILEB);
            }
            #pragma unroll
            for (int f = 0; f < 2; f++)
                #pragma unroll
                for (int p = 0; p < 2; p++)
                    #pragma unroll
                    for (int nb = 0; nb < 2; nb++) {
                        float* cc = acc[f][p*2+nb];
                        MMA16816(cc, ah[f][0],ah[f][1],ah[f][2],ah[f][3],
                                 bh[p][nb], bh[p][nb+2]);
                        MMA16816(cc, al[f][0],al[f][1],al[f][2],al[f][3],
                                 bh[p][nb], bh[p][nb+2]);
                        MMA16816(cc, ah[f][0],ah[f][1],ah[f][2],ah[f][3],
                                 bl[p][nb], bl[p][nb+2]);
                    }
        }
        __syncthreads();          // done reading buf before overwrite / reuse
        if (more) {
            store_chunk(buf ^ 1, va, vb);
            __syncthreads();
        }
    }

    // ---- epilogue: acc -> staging smem [128][132] fp32 -> global ----
    float* stg = (float*)dsm;
    const int erow = lane >> 2, ecol2 = (lane & 3) * 2;
    #pragma unroll
    for (int f = 0; f < 2; f++)
        #pragma unroll
        for (int p = 0; p < 2; p++)
            #pragma unroll
            for (int nb = 0; nb < 2; nb++) {
                int r = warp_m*32 + f*16 + erow;
                int cl = warp_n*32 + p*16 + nb*8 + ecol2;
                float* cc = acc[f][p*2+nb];
                *(float2*)&stg[r*132 + cl]       = make_float2(cc[0], cc[1]);
                *(float2*)&stg[(r+8)*132 + cl]   = make_float2(cc[2], cc[3]);
            }
    __syncthreads();

    if (EPI == 1) {
        #pragma unroll
        for (int i = 0; i < 32; i++) {
            int idx = tid + i * 512;
            int m = idx & 127, j = idx >> 7;
            float v = stg[m*132 + j] + bias[n0 + j];
            int mg = m0 + m;
            int b  = mg >> 11, s = mg & (SS - 1);
            ((uint32_t*)Cout)[((size_t)b * DD + (n0 + j)) * SS + s] = split_pack(v);
        }
    } else {
        #pragma unroll
        for (int i = 0; i < 32; i++) {
            int idx = tid + i * 512;
            int j = idx & 127, m = idx >> 7;
            float v = stg[m*132 + j];
            uint32_t ov;
            if (EPI == 0) ov = split_pack(v + bias[n0 + j]);
            else          ov = __float_as_uint(v);
            ((uint32_t*)Cout)[(size_t)z * sC + (size_t)(m0 + m) * ldc + n0 + j] = ov;
        }
    }
}

// ---------------------------------------------------------------------------
// fp32 -> packed hi/lo bf16 conversion
// ---------------------------------------------------------------------------
__global__ __launch_bounds__(256)
void conv_k(const float* __restrict__ in, uint32_t* __restrict__ outp, int n4)
{
    int i = blockIdx.x * 256 + threadIdx.x;
    if (i >= n4) return;
    float4 v = ((const float4*)in)[i];
    uint4 o;
    o.x = split_pack(v.x); o.y = split_pack(v.y);
    o.z = split_pack(v.z); o.w = split_pack(v.w);
    ((uint4*)outp)[i] = o;
}

// ---------------------------------------------------------------------------
// Rowwise softmax over 2048 fp32 logits, writes packed hi/lo bf16 in place.
// ---------------------------------------------------------------------------
__global__ __launch_bounds__(256)
void softmax_k()
{
    float* p = g_S + (size_t)blockIdx.x * SS;
    uint32_t* po = (uint32_t*)p;
    const int t = threadIdx.x;
    const int lane = t & 31, w = t >> 5;
    __shared__ float red[8];

    float v[8];
    float mx = -3.4e38f;
    #pragma unroll
    for (int i = 0; i < 8; i++) { v[i] = p[t + i * 256]; mx = fmaxf(mx, v[i]); }
    #pragma unroll
    for (int o = 16; o; o >>= 1) mx = fmaxf(mx, __shfl_xor_sync(0xffffffffu, mx, o));
    if (lane == 0) red[w] = mx;
    __syncthreads();
    float m = red[0];
    #pragma unroll
    for (int i = 1; i < 8; i++) m = fmaxf(m, red[i]);

    float s = 0.f;
    #pragma unroll
    for (int i = 0; i < 8; i++) { v[i] = expf(v[i] - m); s += v[i]; }
    #pragma unroll
    for (int o = 16; o; o >>= 1) s += __shfl_xor_sync(0xffffffffu, s, o);
    __syncthreads();
    if (lane == 0) red[w] = s;
    __syncthreads();
    s = 0.f;
    #pragma unroll
    for (int i = 0; i < 8; i++) s += red[i];

    const float inv = 1.0f / s;
    #pragma unroll
    for (int i = 0; i < 8; i++) po[t + i * 256] = split_pack(v[i] * inv);
}

// ---------------------------------------------------------------------------
extern "C" void kernel_launch(void* const* d_in, const int* in_sizes, int n_in,
                              void* d_out, int out_size)
{
    const float* x  = (const float*)d_in[0];
    const float* Wq = (const float*)d_in[1];
    const float* bq = (const float*)d_in[2];
    const float* Wk = (const float*)d_in[3];
    const float* bk = (const float*)d_in[4];
    const float* Wv = (const float*)d_in[5];
    const float* bv = (const float*)d_in[6];
    float* out = (float*)d_out;

    uint32_t *xp, *Wqp, *Wkp, *Wvp, *Qp, *Kp, *Vtp;
    float* Sp;
    cudaGetSymbolAddress((void**)&xp,  g_xp);
    cudaGetSymbolAddress((void**)&Wqp, g_Wqp);
    cudaGetSymbolAddress((void**)&Wkp, g_Wkp);
    cudaGetSymbolAddress((void**)&Wvp, g_Wvp);
    cudaGetSymbolAddress((void**)&Qp,  g_Qp);
    cudaGetSymbolAddress((void**)&Kp,  g_Kp);
    cudaGetSymbolAddress((void**)&Vtp, g_Vtp);
    cudaGetSymbolAddress((void**)&Sp,  g_S);

    cudaFuncSetAttribute(gemm_t<0>, cudaFuncAttributeMaxDynamicSharedMemorySize, SMEMSZ);
    cudaFuncSetAttribute(gemm_t<1>, cudaFuncAttributeMaxDynamicSharedMemorySize, SMEMSZ);
    cudaFuncSetAttribute(gemm_t<2>, cudaFuncAttributeMaxDynamicSharedMemorySize, SMEMSZ);

    // 0) split-pack x and weights
    conv_k<<<(M1 * DD / 4 + 255) / 256, 256>>>(x,  xp,  M1 * DD / 4);
    conv_k<<<(DD * DD / 4 + 255) / 256, 256>>>(Wq, Wqp, DD * DD / 4);
    conv_k<<<(DD * DD / 4 + 255) / 256, 256>>>(Wk, Wkp, DD * DD / 4);
    conv_k<<<(DD * DD / 4 + 255) / 256, 256>>>(Wv, Wvp, DD * DD / 4);

    // 1) projections: [8192,1024] x [1024,1024]^T (+bias) -> packed Q/K, V^T
    dim3 gp(DD / 128, M1 / 128, 1);
    gemm_t<0><<<gp, 512, SMEMSZ>>>(xp, Wqp, bq, Qp,  DD, DD, 0, 0, 0);
    gemm_t<0><<<gp, 512, SMEMSZ>>>(xp, Wkp, bk, Kp,  DD, DD, 0, 0, 0);
    gemm_t<1><<<gp, 512, SMEMSZ>>>(xp, Wvp, bv, Vtp, DD, DD, 0, 0, 0);

    // 2) scores[b] = Q_b @ K_b^T -> fp32 logits
    dim3 gs(SS / 128, SS / 128, BB);
    gemm_t<2><<<gs, 512, SMEMSZ>>>(Qp, Kp, nullptr, Sp, DD, SS,
                                   (long)SS * DD, (long)SS * DD, (long)SS * SS);

    // 3) softmax rows -> packed P in place
    softmax_k<<<BB * SS, 256>>>();

    // 4) out[b] = P_b @ (V_b^T)^T : NT GEMM with Vt (K = seq)
    dim3 gv(DD / 128, SS / 128, BB);
    gemm_t<2><<<gv, 512, SMEMSZ>>>((const uint32_t*)Sp, Vtp, nullptr, out, SS, DD,
                                   (long)SS * SS, (long)DD * SS, (long)SS * DD);
}

// round 4
// speedup vs baseline: 3.9536x; 1.0128x over previous
#include <cuda_runtime.h>
#include <cuda_bf16.h>
#include <stdint.h>
#include <math.h>

#define BB 4
#define SS 2048
#define DD 1024
#define M1 (BB*SS)

// ---------------------------------------------------------------------------
// Scratch (device globals). hi/lo bf16 stored as SEPARATE planes so the GEMM
// mainloop can cp.async them straight into smem with no de-interleave.
// ---------------------------------------------------------------------------
__device__ __nv_bfloat16 g_xh [(size_t)M1*DD],  g_xl [(size_t)M1*DD];
__device__ __nv_bfloat16 g_Wqh[(size_t)DD*DD],  g_Wql[(size_t)DD*DD];
__device__ __nv_bfloat16 g_Wkh[(size_t)DD*DD],  g_Wkl[(size_t)DD*DD];
__device__ __nv_bfloat16 g_Wvh[(size_t)DD*DD],  g_Wvl[(size_t)DD*DD];
__device__ __nv_bfloat16 g_Qh [(size_t)M1*DD],  g_Ql [(size_t)M1*DD];
__device__ __nv_bfloat16 g_Kh [(size_t)M1*DD],  g_Kl [(size_t)M1*DD];
__device__ __nv_bfloat16 g_Vth[(size_t)BB*DD*SS], g_Vtl[(size_t)BB*DD*SS]; // [b][d][s]
__device__ float         g_S  [(size_t)BB*SS*SS];                          // logits
__device__ __nv_bfloat16 g_Ph [(size_t)BB*SS*SS], g_Pl [(size_t)BB*SS*SS]; // softmax out

// ---------------------------------------------------------------------------
__device__ __forceinline__ uint32_t s2u(const void* p){
    uint32_t a;
    asm("{ .reg .u64 t; cvta.to.shared.u64 t, %1; cvt.u32.u64 %0, t; }" : "=r"(a) : "l"(p));
    return a;
}
__device__ __forceinline__ void split2(float v, __nv_bfloat16& h, __nv_bfloat16& l){
    h = __float2bfloat16(v);
    l = __float2bfloat16(v - __bfloat162float(h));
}

#define LDSM4(r0,r1,r2,r3,a) \
    asm volatile("ldmatrix.sync.aligned.m8n8.x4.shared.b16 {%0,%1,%2,%3}, [%4];" \
        : "=r"(r0),"=r"(r1),"=r"(r2),"=r"(r3) : "r"(a))

#define MMA16816(c,a0,a1,a2,a3,b0,b1) \
    asm volatile("mma.sync.aligned.m16n8k16.row.col.f32.bf16.bf16.f32 " \
        "{%0,%1,%2,%3},{%4,%5,%6,%7},{%8,%9},{%0,%1,%2,%3};" \
        : "+f"((c)[0]),"+f"((c)[1]),"+f"((c)[2]),"+f"((c)[3]) \
        : "r"(a0),"r"(a1),"r"(a2),"r"(a3),"r"(b0),"r"(b1))

#define CP16(dst,src) \
    asm volatile("cp.async.cg.shared.global [%0], [%1], 16;" :: "r"(dst), "l"(src) : "memory")
#define CP_COMMIT() asm volatile("cp.async.commit_group;" ::: "memory")
#define CP_WAIT1()  asm volatile("cp.async.wait_group 1;" ::: "memory")
#define CP_WAIT0()  asm volatile("cp.async.wait_group 0;" ::: "memory")

// ---------------------------------------------------------------------------
// HMMA GEMM, C[m,n] = sum_k A[m,k]*B[n,k], A/B given as hi+lo bf16 planes
// (K-major, row stride = Kg). CTA 128x128, 512 thr (16 warps, 4x4), warp tile
// 32x32. KC=64, 3-stage cp.async pipeline, single __syncthreads per chunk.
// 3 products: Ah*Bh + Al*Bh + Ah*Bl, fp32 accum.
// EPI 0: +bias -> split planes C0/C1 (row-major, ldc)
// EPI 1: +bias -> split planes, transposed to [b][dim][seq]
// EPI 2: raw fp32 -> C0
// ---------------------------------------------------------------------------
#define KC 64
#define PITCHB 144                    // 128B data + 16B pad per row
#define TILEB (128*PITCHB)            // 18432
#define STAGEB (4*TILEB)              // Ah,Al,Bh,Bl = 73728
#define SMEMSZ (3*STAGEB)             // 221184

template<int EPI>
__global__ __launch_bounds__(512, 1)
void gemm_t(const __nv_bfloat16* __restrict__ Ah, const __nv_bfloat16* __restrict__ Al,
            const __nv_bfloat16* __restrict__ Bh, const __nv_bfloat16* __restrict__ Bl,
            const float* __restrict__ bias, void* __restrict__ C0, void* __restrict__ C1,
            int Kg, int ldc, long sA, long sB, long sC)
{
    extern __shared__ __align__(128) char dsm[];
    const int tid = threadIdx.x;
    const int wid = tid >> 5, lane = tid & 31;
    const int warp_m = wid & 3, warp_n = wid >> 2;
    const int m0 = blockIdx.y * 128, n0 = blockIdx.x * 128, z = blockIdx.z;

    const __nv_bfloat16* pl[4] = {
        Ah + (size_t)z * sA + (size_t)m0 * Kg,
        Al + (size_t)z * sA + (size_t)m0 * Kg,
        Bh + (size_t)z * sB + (size_t)n0 * Kg,
        Bl + (size_t)z * sB + (size_t)n0 * Kg };

    const uint32_t sb = s2u(dsm);
    const int gr = tid >> 3, gq = tid & 7;     // 64 rows x 8 16B-cols per pass

    auto issue = [&](int c, int s){
        const int kc0 = c * KC;
        const uint32_t st = sb + s * STAGEB;
        #pragma unroll
        for (int t = 0; t < 4; t++)
            #pragma unroll
            for (int j = 0; j < 2; j++){
                int row = gr + j * 64;
                const void* src = pl[t] + (size_t)row * Kg + kc0 + gq * 8;
                uint32_t dst = st + t * TILEB + row * PITCHB + gq * 16;
                CP16(dst, src);
            }
        CP_COMMIT();
    };

    const int lrow = lane & 15, lph = lane >> 4;
    uint32_t aA[2], aB[2];
    #pragma unroll
    for (int f = 0; f < 2; f++)
        aA[f] = sb + (warp_m*32 + f*16 + lrow) * PITCHB + lph * 16;
    #pragma unroll
    for (int p = 0; p < 2; p++)
        aB[p] = sb + 2*TILEB + (warp_n*32 + p*16 + lrow) * PITCHB + lph * 16;

    float acc[2][4][4];
    #pragma unroll
    for (int f = 0; f < 2; f++)
        #pragma unroll
        for (int b = 0; b < 4; b++)
            #pragma unroll
            for (int j = 0; j < 4; j++) acc[f][b][j] = 0.f;

    const int NC = Kg / KC;
    issue(0, 0);
    issue(1, 1);

    for (int c = 0; c < NC; c++){
        if (c < NC - 1) CP_WAIT1(); else CP_WAIT0();
        __syncthreads();
        if (c + 2 < NC) issue(c + 2, (c + 2) % 3);

        const uint32_t so = (c % 3) * STAGEB;
        #pragma unroll
        for (int ks = 0; ks < 4; ks++){
            const uint32_t ko = ks * 32;
            uint32_t ah[2][4], al[2][4], bh[2][4], bl[2][4];
            #pragma unroll
            for (int f = 0; f < 2; f++){
                LDSM4(ah[f][0],ah[f][1],ah[f][2],ah[f][3], aA[f] + so + ko);
                LDSM4(al[f][0],al[f][1],al[f][2],al[f][3], aA[f] + so + ko + TILEB);
            }
            #pragma unroll
            for (int p = 0; p < 2; p++){
                LDSM4(bh[p][0],bh[p][1],bh[p][2],bh[p][3], aB[p] + so + ko);
                LDSM4(bl[p][0],bl[p][1],bl[p][2],bl[p][3], aB[p] + so + ko + TILEB);
            }
            #pragma unroll
            for (int f = 0; f < 2; f++)
                #pragma unroll
                for (int p = 0; p < 2; p++)
                    #pragma unroll
                    for (int nb = 0; nb < 2; nb++){
                        float* cc = acc[f][p*2+nb];
                        MMA16816(cc, ah[f][0],ah[f][1],ah[f][2],ah[f][3],
                                 bh[p][nb], bh[p][nb+2]);
                        MMA16816(cc, al[f][0],al[f][1],al[f][2],al[f][3],
                                 bh[p][nb], bh[p][nb+2]);
                        MMA16816(cc, ah[f][0],ah[f][1],ah[f][2],ah[f][3],
                                 bl[p][nb], bl[p][nb+2]);
                    }
        }
    }
    __syncthreads();

    // ---- epilogue: acc -> staging smem [128][132] fp32 -> global ----
    float* stg = (float*)dsm;
    const int erow = lane >> 2, ecol2 = (lane & 3) * 2;
    #pragma unroll
    for (int f = 0; f < 2; f++)
        #pragma unroll
        for (int p = 0; p < 2; p++)
            #pragma unroll
            for (int nb = 0; nb < 2; nb++){
                int r  = warp_m*32 + f*16 + erow;
                int cl = warp_n*32 + p*16 + nb*8 + ecol2;
                float* cc = acc[f][p*2+nb];
                *(float2*)&stg[r*132 + cl]     = make_float2(cc[0], cc[1]);
                *(float2*)&stg[(r+8)*132 + cl] = make_float2(cc[2], cc[3]);
            }
    __syncthreads();

    if (EPI == 0){
        #pragma unroll
        for (int i = 0; i < 32; i++){
            int idx = tid + i * 512;
            int j = idx & 127, m = idx >> 7;
            float v = stg[m*132 + j] + bias[n0 + j];
            __nv_bfloat16 h, l; split2(v, h, l);
            size_t o = (size_t)(m0 + m) * ldc + n0 + j;
            ((__nv_bfloat16*)C0)[o] = h;
            ((__nv_bfloat16*)C1)[o] = l;
        }
    } else if (EPI == 1){
        #pragma unroll
        for (int i = 0; i < 32; i++){
            int idx = tid + i * 512;
            int m = idx & 127, j = idx >> 7;
            float v = stg[m*132 + j] + bias[n0 + j];
            __nv_bfloat16 h, l; split2(v, h, l);
            int mg = m0 + m;
            int b  = mg >> 11, s = mg & (SS - 1);
            size_t o = ((size_t)b * DD + (n0 + j)) * SS + s;
            ((__nv_bfloat16*)C0)[o] = h;
            ((__nv_bfloat16*)C1)[o] = l;
        }
    } else {
        #pragma unroll
        for (int i = 0; i < 32; i++){
            int idx = tid + i * 512;
            int j = idx & 127, m = idx >> 7;
            ((float*)C0)[(size_t)z * sC + (size_t)(m0 + m) * ldc + n0 + j] = stg[m*132 + j];
        }
    }
}

// ---------------------------------------------------------------------------
// fp32 -> hi/lo bf16 planes
// ---------------------------------------------------------------------------
__global__ __launch_bounds__(256)
void conv_k(const float* __restrict__ in, __nv_bfloat16* __restrict__ oh,
            __nv_bfloat16* __restrict__ ol, int n4)
{
    int i = blockIdx.x * 256 + threadIdx.x;
    if (i >= n4) return;
    float4 v = ((const float4*)in)[i];
    __nv_bfloat16 h0,h1,h2,h3,l0,l1,l2,l3;
    split2(v.x,h0,l0); split2(v.y,h1,l1); split2(v.z,h2,l2); split2(v.w,h3,l3);
    uint2 H, L;
    H.x = (uint32_t)__bfloat16_as_ushort(h0) | ((uint32_t)__bfloat16_as_ushort(h1)<<16);
    H.y = (uint32_t)__bfloat16_as_ushort(h2) | ((uint32_t)__bfloat16_as_ushort(h3)<<16);
    L.x = (uint32_t)__bfloat16_as_ushort(l0) | ((uint32_t)__bfloat16_as_ushort(l1)<<16);
    L.y = (uint32_t)__bfloat16_as_ushort(l2) | ((uint32_t)__bfloat16_as_ushort(l3)<<16);
    ((uint2*)oh)[i] = H;
    ((uint2*)ol)[i] = L;
}

// ---------------------------------------------------------------------------
// Rowwise softmax over 2048 fp32 logits -> hi/lo bf16 planes.
// ---------------------------------------------------------------------------
__global__ __launch_bounds__(256)
void softmax_k()
{
    const size_t row = blockIdx.x;
    float* p = g_S + row * SS;
    __nv_bfloat16* ph = g_Ph + row * SS;
    __nv_bfloat16* pxl = g_Pl + row * SS;
    const int t = threadIdx.x;
    const int lane = t & 31, w = t >> 5;
    __shared__ float red[8];

    float v[8];
    float mx = -3.4e38f;
    #pragma unroll
    for (int i = 0; i < 8; i++){ v[i] = p[t + i*256]; mx = fmaxf(mx, v[i]); }
    #pragma unroll
    for (int o = 16; o; o >>= 1) mx = fmaxf(mx, __shfl_xor_sync(0xffffffffu, mx, o));
    if (lane == 0) red[w] = mx;
    __syncthreads();
    float m = red[0];
    #pragma unroll
    for (int i = 1; i < 8; i++) m = fmaxf(m, red[i]);

    float s = 0.f;
    #pragma unroll
    for (int i = 0; i < 8; i++){ v[i] = expf(v[i] - m); s += v[i]; }
    #pragma unroll
    for (int o = 16; o; o >>= 1) s += __shfl_xor_sync(0xffffffffu, s, o);
    __syncthreads();
    if (lane == 0) red[w] = s;
    __syncthreads();
    s = 0.f;
    #pragma unroll
    for (int i = 0; i < 8; i++) s += red[i];

    const float inv = 1.0f / s;
    #pragma unroll
    for (int i = 0; i < 8; i++){
        __nv_bfloat16 h, l; split2(v[i] * inv, h, l);
        ph[t + i*256] = h;
        pxl[t + i*256] = l;
    }
}

// ---------------------------------------------------------------------------
extern "C" void kernel_launch(void* const* d_in, const int* in_sizes, int n_in,
                              void* d_out, int out_size)
{
    const float* x  = (const float*)d_in[0];
    const float* Wq = (const float*)d_in[1];
    const float* bq = (const float*)d_in[2];
    const float* Wk = (const float*)d_in[3];
    const float* bk = (const float*)d_in[4];
    const float* Wv = (const float*)d_in[5];
    const float* bv = (const float*)d_in[6];
    float* out = (float*)d_out;

    __nv_bfloat16 *xh,*xl,*Wqh,*Wql,*Wkh,*Wkl,*Wvh,*Wvl,*Qh,*Ql,*Kh,*Kl,*Vth,*Vtl,*Ph,*Pl;
    float* Sp;
    cudaGetSymbolAddress((void**)&xh,  g_xh);  cudaGetSymbolAddress((void**)&xl,  g_xl);
    cudaGetSymbolAddress((void**)&Wqh, g_Wqh); cudaGetSymbolAddress((void**)&Wql, g_Wql);
    cudaGetSymbolAddress((void**)&Wkh, g_Wkh); cudaGetSymbolAddress((void**)&Wkl, g_Wkl);
    cudaGetSymbolAddress((void**)&Wvh, g_Wvh); cudaGetSymbolAddress((void**)&Wvl, g_Wvl);
    cudaGetSymbolAddress((void**)&Qh,  g_Qh);  cudaGetSymbolAddress((void**)&Ql,  g_Ql);
    cudaGetSymbolAddress((void**)&Kh,  g_Kh);  cudaGetSymbolAddress((void**)&Kl,  g_Kl);
    cudaGetSymbolAddress((void**)&Vth, g_Vth); cudaGetSymbolAddress((void**)&Vtl, g_Vtl);
    cudaGetSymbolAddress((void**)&Ph,  g_Ph);  cudaGetSymbolAddress((void**)&Pl,  g_Pl);
    cudaGetSymbolAddress((void**)&Sp,  g_S);

    cudaFuncSetAttribute(gemm_t<0>, cudaFuncAttributeMaxDynamicSharedMemorySize, SMEMSZ);
    cudaFuncSetAttribute(gemm_t<1>, cudaFuncAttributeMaxDynamicSharedMemorySize, SMEMSZ);
    cudaFuncSetAttribute(gemm_t<2>, cudaFuncAttributeMaxDynamicSharedMemorySize, SMEMSZ);

    // 0) split x and weights into planes
    conv_k<<<(M1*DD/4 + 255)/256, 256>>>(x,  xh,  xl,  M1*DD/4);
    conv_k<<<(DD*DD/4 + 255)/256, 256>>>(Wq, Wqh, Wql, DD*DD/4);
    conv_k<<<(DD*DD/4 + 255)/256, 256>>>(Wk, Wkh, Wkl, DD*DD/4);
    conv_k<<<(DD*DD/4 + 255)/256, 256>>>(Wv, Wvh, Wvl, DD*DD/4);

    // 1) projections
    dim3 gp(DD/128, M1/128, 1);
    gemm_t<0><<<gp, 512, SMEMSZ>>>(xh, xl, Wqh, Wql, bq, Qh,  Ql,  DD, DD, 0, 0, 0);
    gemm_t<0><<<gp, 512, SMEMSZ>>>(xh, xl, Wkh, Wkl, bk, Kh,  Kl,  DD, DD, 0, 0, 0);
    gemm_t<1><<<gp, 512, SMEMSZ>>>(xh, xl, Wvh, Wvl, bv, Vth, Vtl, DD, DD, 0, 0, 0);

    // 2) scores[b] = Q_b @ K_b^T -> fp32 logits
    dim3 gs(SS/128, SS/128, BB);
    gemm_t<2><<<gs, 512, SMEMSZ>>>(Qh, Ql, Kh, Kl, nullptr, Sp, nullptr, DD, SS,
                                   (long)SS*DD, (long)SS*DD, (long)SS*SS);

    // 3) softmax -> P planes
    softmax_k<<<BB*SS, 256>>>();

    // 4) out[b] = P_b @ Vt_b^T  (K = seq = 2048)
    dim3 gv(DD/128, SS/128, BB);
    gemm_t<2><<<gv, 512, SMEMSZ>>>(Ph, Pl, Vth, Vtl, nullptr, out, nullptr, SS, DD,
                                   (long)SS*SS, (long)DD*SS, (long)SS*DD);
}